// round 5
// baseline (speedup 1.0000x reference)
#include <cuda_runtime.h>
#include <math_constants.h>

#define MAXB 256
#define TPB  256
#define INF_BITS 0x7F800000u
#define MAXGRID 2048

// Persistent scratch (__device__ globals; no allocations allowed).
__device__ unsigned g_tmax_bits = 0u;   // idempotent across replays (never reset)
__device__ float    g_bins_sorted[MAXB];
__device__ unsigned g_cand_below[MAXB]; // re-INF'd by K1 block 0 each launch
__device__ unsigned g_cand_above[MAXB];
__device__ unsigned g_done;             // reset by K1 block 0 each launch
__device__ double   g_part[MAXGRID];

// ---------------------------------------------------------------------------
// K1: blocks 1..G-1 -> global target max (float4 strided, bit atomicMax).
//     block 0       -> bin prep (max, normalize, rank-sort) + state init.
// ---------------------------------------------------------------------------
__global__ __launch_bounds__(TPB)
void k1_tmax_prep(const float* __restrict__ bins, int nb,
                  const float* __restrict__ tgt, int n) {
    const int tid = threadIdx.x;
    __shared__ float red[TPB / 32];

    if (blockIdx.x == 0) {
        __shared__ float fraw[MAXB];
        __shared__ float ss[MAXB];
        float bm = -CUDART_INF_F;
        for (int i = tid; i < nb; i += TPB) {
            float b = bins[i];
            fraw[i] = b;
            bm = fmaxf(bm, b);
        }
        for (int o = 16; o; o >>= 1) bm = fmaxf(bm, __shfl_xor_sync(0xffffffffu, bm, o));
        if ((tid & 31) == 0) red[tid >> 5] = bm;
        __syncthreads();
        float m = red[0];
        #pragma unroll
        for (int i = 1; i < TPB / 32; i++) m = fmaxf(m, red[i]);
        float inv_bm = 1.0f / m;
        for (int i = tid; i < nb; i += TPB) fraw[i] *= inv_bm;
        __syncthreads();
        // Rank sort (nb<=256).
        for (int i = tid; i < nb; i += TPB) {
            float v = fraw[i];
            int rank = 0;
            for (int j = 0; j < nb; j++) {
                float u = fraw[j];
                rank += (u < v) || (u == v && j < i);
            }
            ss[rank] = v;
        }
        __syncthreads();
        for (int i = tid; i < nb; i += TPB) {
            g_bins_sorted[i] = ss[i];
            g_cand_below[i]  = INF_BITS;
            g_cand_above[i]  = INF_BITS;
        }
        if (tid == 0) g_done = 0u;
    } else {
        const int nblk = gridDim.x - 1;
        const int bid  = blockIdx.x - 1;
        const int stride = nblk * TPB;
        const int n4 = n >> 2;
        const float4* t4 = (const float4*)tgt;
        float m = 0.0f;
        for (int i = bid * TPB + tid; i < n4; i += stride) {
            float4 v = t4[i];
            m = fmaxf(m, isfinite(v.x) ? v.x : 0.f);
            m = fmaxf(m, isfinite(v.y) ? v.y : 0.f);
            m = fmaxf(m, isfinite(v.z) ? v.z : 0.f);
            m = fmaxf(m, isfinite(v.w) ? v.w : 0.f);
        }
        for (int i = (n4 << 2) + bid * TPB + tid; i < n; i += stride) {
            float v = tgt[i];
            m = fmaxf(m, isfinite(v) ? v : 0.f);
        }
        for (int o = 16; o; o >>= 1) m = fmaxf(m, __shfl_xor_sync(0xffffffffu, m, o));
        if ((tid & 31) == 0) red[tid >> 5] = m;
        __syncthreads();
        if (tid == 0) {
            float mm = red[0];
            #pragma unroll
            for (int i = 1; i < TPB / 32; i++) mm = fmaxf(mm, red[i]);
            atomicMax(&g_tmax_bits, __float_as_uint(mm)); // positive floats: bit order
        }
    }
}

// ---------------------------------------------------------------------------
// K2: main pass (targets are L2-hot from K1). Binary search in shared,
// shared atomicMin staging, RED global merge, last block runs final scans.
// ---------------------------------------------------------------------------
__global__ __launch_bounds__(TPB)
void k2_main_final(const float* __restrict__ tgt, int n, int nb,
                   float* __restrict__ out) {
    __shared__ float    sb[MAXB];
    __shared__ unsigned sbel[MAXB];
    __shared__ unsigned sabv[MAXB];
    __shared__ float    red[TPB / 32];
    __shared__ bool     amLast;

    const int tid  = threadIdx.x;
    const int bid  = blockIdx.x;
    const int grid = gridDim.x;
    const int n4   = n >> 2;

    if (tid < nb) {
        sb[tid]   = g_bins_sorted[tid];
        sbel[tid] = INF_BITS;
        sabv[tid] = INF_BITS;
    }
    if (tid == 0) amLast = false;
    __syncthreads();

    const float inv = 1.0f / __uint_as_float(g_tmax_bits);
    float acc = 0.0f;

    auto proc = [&](float raw) {
        float t = raw * inv;
        if (!isfinite(t)) return;
        // branchless upper_bound: lo = count of bins <= t
        int lo = 0;
        #pragma unroll
        for (int step = 128; step; step >>= 1) {
            int cand = lo + step;
            if (cand <= nb && sb[cand - 1] <= t) lo = cand;
        }
        float best = CUDART_INF_F;
        if (lo > 0) {
            float d = t - sb[lo - 1];
            best = d;
            atomicMin(&sabv[lo - 1], __float_as_uint(d));
        }
        if (lo < nb) {
            float d = sb[lo] - t;
            best = fminf(best, d);
            atomicMin(&sbel[lo], __float_as_uint(d));
        }
        if (isfinite(best)) acc += best * best;
    };

    {
        const float4* t4 = (const float4*)tgt;
        const int stride = grid * TPB;
        for (int i = bid * TPB + tid; i < n4; i += stride) {
            float4 v = t4[i];
            proc(v.x); proc(v.y); proc(v.z); proc(v.w);
        }
        if (bid == 0) {
            for (int i = (n4 << 2) + tid; i < n; i += TPB) proc(tgt[i]);
        }
    }

    // dir2 block partial
    for (int o = 16; o; o >>= 1) acc += __shfl_xor_sync(0xffffffffu, acc, o);
    if ((tid & 31) == 0) red[tid >> 5] = acc;
    __syncthreads();
    if (tid == 0) {
        double s = 0.0;
        #pragma unroll
        for (int i = 0; i < TPB / 32; i++) s += (double)red[i];
        g_part[bid] = s;
    }

    // merge candidate mins to global (no return value -> RED)
    if (tid < nb) {
        if (sbel[tid] != INF_BITS) atomicMin(&g_cand_below[tid], sbel[tid]);
        if (sabv[tid] != INF_BITS) atomicMin(&g_cand_above[tid], sabv[tid]);
    }

    // last block does the final scans + output
    __threadfence();
    __syncthreads();
    if (tid == 0) amLast = (atomicAdd(&g_done, 1u) == (unsigned)(grid - 1));
    __syncthreads();
    if (!amLast) return;

    // d_above[j] = min_{k>=j}(cand_above[k]+b[k]) - b[j]  (suffix min)
    // d_below[j] = min_{k<=j}(cand_below[k]-b[k]) + b[j]  (prefix min)
    float* fA = (float*)sabv;
    float* fB = (float*)sbel;
    if (tid < nb) {
        float b  = sb[tid];
        float ca = __uint_as_float(*((volatile unsigned*)&g_cand_above[tid]));
        float cb = __uint_as_float(*((volatile unsigned*)&g_cand_below[tid]));
        fA[tid] = ca + b;
        fB[tid] = cb - b;
    }
    __syncthreads();
    for (int off = 1; off < nb; off <<= 1) {
        float a = CUDART_INF_F, bp = CUDART_INF_F;
        if (tid < nb) {
            if (tid + off < nb) a  = fA[tid + off];
            if (tid >= off)     bp = fB[tid - off];
        }
        __syncthreads();
        if (tid < nb) {
            fA[tid] = fminf(fA[tid], a);
            fB[tid] = fminf(fB[tid], bp);
        }
        __syncthreads();
    }

    double total = 0.0;
    if (tid < nb) {
        float nn = fminf(fA[tid] - sb[tid], fB[tid] + sb[tid]);
        if (isfinite(nn)) total = (double)nn * (double)nn;
    }
    for (int i = tid; i < grid; i += TPB) total += g_part[i];

    for (int o = 16; o; o >>= 1) total += __shfl_xor_sync(0xffffffffu, total, o);
    __shared__ double sd[TPB / 32];
    if ((tid & 31) == 0) sd[tid >> 5] = total;
    __syncthreads();
    if (tid == 0) {
        double s = 0.0;
        #pragma unroll
        for (int i = 0; i < TPB / 32; i++) s += sd[i];
        out[0] = (float)s;
    }
}

// ---------------------------------------------------------------------------
extern "C" void kernel_launch(void* const* d_in, const int* in_sizes, int n_in,
                              void* d_out, int out_size) {
    const float* tgt;
    const float* bins;
    int nT, nB;
    if (in_sizes[0] >= in_sizes[1]) {
        tgt = (const float*)d_in[0]; nT = in_sizes[0];
        bins = (const float*)d_in[1]; nB = in_sizes[1];
    } else {
        tgt = (const float*)d_in[1]; nT = in_sizes[1];
        bins = (const float*)d_in[0]; nB = in_sizes[0];
    }
    if (nB > MAXB) nB = MAXB;  // defensive; actual nB = 256

    int n4 = nT >> 2;
    int blocks = (n4 + TPB - 1) / TPB;   // one float4 per thread
    if (blocks < 1) blocks = 1;
    if (blocks > MAXGRID) blocks = MAXGRID;  // falls back to strided loop

    k1_tmax_prep<<<149, TPB>>>(bins, nB, tgt, nT);
    k2_main_final<<<blocks, TPB>>>(tgt, nT, nB, (float*)d_out);
}